// round 1
// baseline (speedup 1.0000x reference)
#include <cuda_runtime.h>
#include <cuda_bf16.h>

// Problem constants
#define B_   16      // batch
#define N_   1152    // primary caps
#define DP   8       // dim primary
#define M_   10      // digit caps
#define DD   16      // dim digit
#define NC   36      // n-chunks (grid.x)
#define CH   32      // n per chunk
#define NN   16      // n per sub-chunk (staged in SMEM)
#define NSUB (CH / NN)
#define SSTR 132     // padded shared stride per nn slice (128 + 4), keeps 16B align, kills conflicts

// Partial sums: [chunk][b][m][d]
__device__ float g_partial[NC * B_ * M_ * DD];

__global__ __launch_bounds__(256) void digitcaps_main(
    const float* __restrict__ u,   // [B, N, DP]
    const float* __restrict__ W,   // [M, N, DD, DP]
    const float* __restrict__ Bp)  // [M, 1, N]
{
    __shared__ float sW[NN * SSTR];   // [nn][d*8+p], stride 132
    __shared__ float sU[NN * SSTR];   // [nn][b*8+p], stride 132
    __shared__ float sBp[NN];

    const int chunk = blockIdx.x;
    const int m     = blockIdx.y;
    const int tid   = threadIdx.x;
    const int nn_g  = tid & 15;         // which nn this thread computes
    const int bg    = (tid >> 4) & 3;   // b group (4 b's)
    const int dg    = tid >> 6;         // d group (4 d's)

    float acc[4][4];
    #pragma unroll
    for (int i = 0; i < 4; ++i)
        #pragma unroll
        for (int j = 0; j < 4; ++j) acc[i][j] = 0.f;

    const int nbase = chunk * CH;

    for (int s = 0; s < NSUB; ++s) {
        const int n0 = nbase + s * NN;

        // ---- stage W tile: 16 n * 128 floats, fully contiguous in GMEM
        {
            const float4* gw = (const float4*)(W + ((size_t)m * N_ + n0) * (DD * DP));
            #pragma unroll
            for (int r = 0; r < 2; ++r) {
                int f  = tid + r * 256;       // 0..511 float4s
                int nn = f >> 5;              // 32 float4 per n
                int k4 = f & 31;
                float4 v = gw[f];
                *(float4*)(&sW[nn * SSTR + k4 * 4]) = v;
            }
        }
        // ---- stage u tile, transposed to [nn][b][p]
        {
            #pragma unroll
            for (int r = 0; r < 2; ++r) {
                int f   = tid + r * 256;      // 0..511 float4s
                int b   = f >> 5;             // 32 float4 per b (16 nn * 8 p / 4)
                int rem = f & 31;
                int nn  = rem >> 1;
                int p4  = (rem & 1) * 4;
                float4 v = *(const float4*)(u + ((size_t)b * N_ + (n0 + nn)) * DP + p4);
                *(float4*)(&sU[nn * SSTR + b * 8 + p4]) = v;
            }
        }
        if (tid < NN) sBp[tid] = 1.0f + Bp[m * N_ + n0 + tid];
        __syncthreads();

        // ---- compute: thread handles nn = nn_g, 4x4 (b,d) register tile
        {
            const float sc = sBp[nn_g];
            const float* uS = &sU[nn_g * SSTR + bg * 32];
            const float* wS = &sW[nn_g * SSTR + dg * 32];

            float ur[4][8];
            #pragma unroll
            for (int i = 0; i < 4; ++i) {
                float4 a0 = *(const float4*)(uS + i * 8);
                float4 a1 = *(const float4*)(uS + i * 8 + 4);
                ur[i][0] = a0.x; ur[i][1] = a0.y; ur[i][2] = a0.z; ur[i][3] = a0.w;
                ur[i][4] = a1.x; ur[i][5] = a1.y; ur[i][6] = a1.z; ur[i][7] = a1.w;
            }
            #pragma unroll
            for (int j = 0; j < 4; ++j) {
                float4 w0 = *(const float4*)(wS + j * 8);
                float4 w1 = *(const float4*)(wS + j * 8 + 4);
                float w[8] = {w0.x, w0.y, w0.z, w0.w, w1.x, w1.y, w1.z, w1.w};
                #pragma unroll
                for (int i = 0; i < 4; ++i) {
                    float dot = 0.f;
                    #pragma unroll
                    for (int p = 0; p < 8; ++p) dot = fmaf(w[p], ur[i][p], dot);
                    acc[i][j] = fmaf(sc, dot, acc[i][j]);
                }
            }
        }
        __syncthreads();
    }

    // ---- reduce over the 16 nn lanes (consecutive tids -> half-warp shuffles)
    #pragma unroll
    for (int i = 0; i < 4; ++i)
        #pragma unroll
        for (int j = 0; j < 4; ++j) {
            float v = acc[i][j];
            #pragma unroll
            for (int off = 8; off >= 1; off >>= 1)
                v += __shfl_down_sync(0xFFFFFFFFu, v, off, 16);
            acc[i][j] = v;
        }

    if (nn_g == 0) {
        #pragma unroll
        for (int i = 0; i < 4; ++i) {
            const int b = bg * 4 + i;
            #pragma unroll
            for (int j = 0; j < 4; ++j) {
                const int d = dg * 4 + j;
                g_partial[((chunk * B_ + b) * M_ + m) * DD + d] = acc[i][j];
            }
        }
    }
}

__global__ __launch_bounds__(192) void digitcaps_squash(float* __restrict__ out)
{
    const int t = threadIdx.x;
    if (t >= B_ * M_) return;
    const int b = t / M_;
    const int m = t % M_;

    float S[DD];
    #pragma unroll
    for (int d = 0; d < DD; ++d) S[d] = 0.f;

    for (int c = 0; c < NC; ++c) {
        const float* p = &g_partial[((c * B_ + b) * M_ + m) * DD];
        #pragma unroll
        for (int d4 = 0; d4 < DD; d4 += 4) {
            float4 v = *(const float4*)(p + d4);
            S[d4 + 0] += v.x; S[d4 + 1] += v.y; S[d4 + 2] += v.z; S[d4 + 3] += v.w;
        }
    }

    float n2 = 0.f;
    #pragma unroll
    for (int d = 0; d < DD; ++d) n2 = fmaf(S[d], S[d], n2);
    const float norm  = sqrtf(n2);
    const float coef  = 1.0f - expf(-norm);
    const float scale = coef / (norm + 1e-7f);

    float* o = out + (size_t)t * DD;
    #pragma unroll
    for (int d4 = 0; d4 < DD; d4 += 4) {
        float4 v;
        v.x = S[d4 + 0] * scale; v.y = S[d4 + 1] * scale;
        v.z = S[d4 + 2] * scale; v.w = S[d4 + 3] * scale;
        *(float4*)(o + d4) = v;
    }
}

extern "C" void kernel_launch(void* const* d_in, const int* in_sizes, int n_in,
                              void* d_out, int out_size)
{
    const float* u  = (const float*)d_in[0];   // primary_caps [16,1152,8]
    const float* W  = (const float*)d_in[1];   // W [10,1152,16,8]
    const float* Bp = (const float*)d_in[2];   // B_prior [10,1,1152]
    float* out = (float*)d_out;                // [16,10,16]

    dim3 grid(NC, M_);
    digitcaps_main<<<grid, 256>>>(u, W, Bp);
    digitcaps_squash<<<1, 192>>>(out);
}

// round 2
// speedup vs baseline: 1.5359x; 1.5359x over previous
#include <cuda_runtime.h>
#include <cuda_bf16.h>

// Problem constants
#define B_   16      // batch
#define N_   1152    // primary caps
#define DP   8       // dim primary
#define M_   10      // digit caps
#define DD   16      // dim digit
#define NC   36      // n-chunks (grid.x)
#define CH   32      // n per chunk
#define NN   16      // n per sub-chunk (staged in SMEM)
#define NSUB (CH / NN)
#define SSTR 132     // padded shared stride per nn slice

// Partial sums: [chunk][b][m][d]
__device__ float g_partial[NC * B_ * M_ * DD];

__global__ __launch_bounds__(256) void digitcaps_main(
    const float* __restrict__ u,   // [B, N, DP]
    const float* __restrict__ W,   // [M, N, DD, DP]
    const float* __restrict__ Bp)  // [M, 1, N]
{
    __shared__ float sW[NN * SSTR];   // [nn][d*8+p]
    __shared__ float sU[NN * SSTR];   // [nn][b*8+p]
    __shared__ float sBp[NN];

    const int chunk = blockIdx.x;
    const int m     = blockIdx.y;
    const int tid   = threadIdx.x;
    const int nn_g  = tid & 15;         // which nn this thread computes
    const int bg    = (tid >> 4) & 3;   // b group (4 b's)
    const int dg    = tid >> 6;         // d group (4 d's)

    float acc[4][4];
    #pragma unroll
    for (int i = 0; i < 4; ++i)
        #pragma unroll
        for (int j = 0; j < 4; ++j) acc[i][j] = 0.f;

    const int nbase = chunk * CH;

    for (int s = 0; s < NSUB; ++s) {
        const int n0 = nbase + s * NN;

        // ---- stage W tile: 16 n * 128 floats, contiguous in GMEM
        {
            const float4* gw = (const float4*)(W + ((size_t)m * N_ + n0) * (DD * DP));
            #pragma unroll
            for (int r = 0; r < 2; ++r) {
                int f  = tid + r * 256;       // 0..511 float4s
                int nn = f >> 5;              // 32 float4 per n
                int k4 = f & 31;
                float4 v = gw[f];
                *(float4*)(&sW[nn * SSTR + k4 * 4]) = v;
            }
        }
        // ---- stage u tile, transposed to [nn][b][p]
        {
            #pragma unroll
            for (int r = 0; r < 2; ++r) {
                int f   = tid + r * 256;      // 0..511 float4s
                int b   = f >> 5;             // 32 float4 per b
                int rem = f & 31;
                int nn  = rem >> 1;
                int p4  = (rem & 1) * 4;
                float4 v = *(const float4*)(u + ((size_t)b * N_ + (n0 + nn)) * DP + p4);
                *(float4*)(&sU[nn * SSTR + b * 8 + p4]) = v;
            }
        }
        if (tid < NN) sBp[tid] = 1.0f + Bp[m * N_ + n0 + tid];
        __syncthreads();

        // ---- compute: thread handles nn = nn_g, 4x4 (b,d) register tile
        {
            const float sc = sBp[nn_g];
            const float* uS = &sU[nn_g * SSTR + bg * 32];
            const float* wS = &sW[nn_g * SSTR + dg * 32];

            float ur[4][8];
            #pragma unroll
            for (int i = 0; i < 4; ++i) {
                float4 a0 = *(const float4*)(uS + i * 8);
                float4 a1 = *(const float4*)(uS + i * 8 + 4);
                ur[i][0] = a0.x; ur[i][1] = a0.y; ur[i][2] = a0.z; ur[i][3] = a0.w;
                ur[i][4] = a1.x; ur[i][5] = a1.y; ur[i][6] = a1.z; ur[i][7] = a1.w;
            }
            #pragma unroll
            for (int j = 0; j < 4; ++j) {
                float4 w0 = *(const float4*)(wS + j * 8);
                float4 w1 = *(const float4*)(wS + j * 8 + 4);
                float w[8] = {w0.x, w0.y, w0.z, w0.w, w1.x, w1.y, w1.z, w1.w};
                #pragma unroll
                for (int i = 0; i < 4; ++i) {
                    float dot = 0.f;
                    #pragma unroll
                    for (int p = 0; p < 8; ++p) dot = fmaf(w[p], ur[i][p], dot);
                    acc[i][j] = fmaf(sc, dot, acc[i][j]);
                }
            }
        }
        __syncthreads();
    }

    // ---- reduce over the 16 nn lanes (half-warp shuffles)
    #pragma unroll
    for (int i = 0; i < 4; ++i)
        #pragma unroll
        for (int j = 0; j < 4; ++j) {
            float v = acc[i][j];
            #pragma unroll
            for (int off = 8; off >= 1; off >>= 1)
                v += __shfl_down_sync(0xFFFFFFFFu, v, off, 16);
            acc[i][j] = v;
        }

    if (nn_g == 0) {
        #pragma unroll
        for (int i = 0; i < 4; ++i) {
            const int b = bg * 4 + i;
            #pragma unroll
            for (int j = 0; j < 4; ++j) {
                const int d = dg * 4 + j;
                g_partial[((chunk * B_ + b) * M_ + m) * DD + d] = acc[i][j];
            }
        }
    }
}

// One CTA per (b,m). 160 threads: t in [0,144) loads one float4 of partials
// (c = t/4, quad = t%4) -> all NC*4 loads issue in parallel (one latency round).
// Then 16 threads reduce over c in shared, shuffle-reduce the norm, write out.
__global__ __launch_bounds__(160) void digitcaps_squash(float* __restrict__ out)
{
    __shared__ float sh[NC * DD];   // [c][d]
    const int bm = blockIdx.x;      // 0..159
    const int b  = bm / M_;
    const int m  = bm % M_;
    const int t  = threadIdx.x;

    if (t < NC * 4) {
        const int c = t >> 2;
        const int q = t & 3;
        float4 v = *(const float4*)(&g_partial[((c * B_ + b) * M_ + m) * DD + q * 4]);
        *(float4*)(&sh[c * DD + q * 4]) = v;
    }
    __syncthreads();

    if (t < DD) {
        float S = 0.f;
        #pragma unroll
        for (int c = 0; c < NC; ++c) S += sh[c * DD + t];

        // sum of squares across the 16 lanes (all within warp 0)
        float n2 = S * S;
        #pragma unroll
        for (int off = 8; off >= 1; off >>= 1)
            n2 += __shfl_xor_sync(0x0000FFFFu, n2, off, 16);

        const float norm  = sqrtf(n2);
        const float coef  = 1.0f - expf(-norm);
        const float scale = coef / (norm + 1e-7f);

        out[bm * DD + t] = S * scale;
    }
}

extern "C" void kernel_launch(void* const* d_in, const int* in_sizes, int n_in,
                              void* d_out, int out_size)
{
    const float* u  = (const float*)d_in[0];   // primary_caps [16,1152,8]
    const float* W  = (const float*)d_in[1];   // W [10,1152,16,8]
    const float* Bp = (const float*)d_in[2];   // B_prior [10,1,1152]
    float* out = (float*)d_out;                // [16,10,16]

    dim3 grid(NC, M_);
    digitcaps_main<<<grid, 256>>>(u, W, Bp);
    digitcaps_squash<<<B_ * M_, 160>>>(out);
}

// round 3
// speedup vs baseline: 1.7887x; 1.1646x over previous
#include <cuda_runtime.h>
#include <cuda_bf16.h>

// Problem constants
#define B_   16      // batch
#define N_   1152    // primary caps
#define DP   8       // dim primary
#define M_   10      // digit caps
#define DD   16      // dim digit
#define CH   16      // n per chunk (one-shot staging, no loop)
#define NC   (N_ / CH)   // 72 chunks
#define NN   16
#define SSTR 132     // padded shared stride per nn slice

// Partials laid out [m][chunk][b*16+d]  -> phase-2 reads are fully contiguous per m
__device__ float    g_partial[M_ * NC * B_ * DD];
__device__ unsigned g_ctr[M_];   // zero-init; atomicInc wraps -> self-resetting per launch

__global__ __launch_bounds__(256) void digitcaps_fused(
    const float* __restrict__ u,   // [B, N, DP]
    const float* __restrict__ W,   // [M, N, DD, DP]
    const float* __restrict__ Bp,  // [M, 1, N]
    float* __restrict__ out)       // [B, M, DD]
{
    __shared__ float sW[NN * SSTR];   // [nn][d*8+p]
    __shared__ float sU[NN * SSTR];   // [nn][b*8+p]
    __shared__ float sBp[NN];
    __shared__ float sOut[B_ * DD];   // staging for coalesced partial write
    __shared__ unsigned sLast;

    const int chunk = blockIdx.x;     // 0..71
    const int m     = blockIdx.y;     // 0..9
    const int tid   = threadIdx.x;
    const int nn_g  = tid & 15;       // nn handled by this thread
    const int bg    = (tid >> 4) & 3; // 4 b's
    const int dg    = tid >> 6;       // 4 d's

    const int n0 = chunk * CH;

    // ---- stage W tile: 16 n * 128 floats, contiguous (512 float4, 2/thread)
    {
        const float4* gw = (const float4*)(W + ((size_t)m * N_ + n0) * (DD * DP));
        #pragma unroll
        for (int r = 0; r < 2; ++r) {
            int f  = tid + r * 256;
            int nn = f >> 5;             // 32 float4 per n
            int k4 = f & 31;
            float4 v = gw[f];
            *(float4*)(&sW[nn * SSTR + k4 * 4]) = v;
        }
    }
    // ---- stage u tile, transposed to [nn][b][p]  (512 float4, 2/thread)
    {
        #pragma unroll
        for (int r = 0; r < 2; ++r) {
            int f   = tid + r * 256;
            int b   = f >> 5;            // 32 float4 per b (16nn * 8p / 4)
            int rem = f & 31;
            int nn  = rem >> 1;
            int p4  = (rem & 1) * 4;
            float4 v = *(const float4*)(u + ((size_t)b * N_ + (n0 + nn)) * DP + p4);
            *(float4*)(&sU[nn * SSTR + b * 8 + p4]) = v;
        }
    }
    if (tid < NN) sBp[tid] = 1.0f + Bp[m * N_ + n0 + tid];
    __syncthreads();

    // ---- compute: thread handles nn = nn_g, 4x4 (b,d) register tile
    float acc[4][4];
    {
        const float sc = sBp[nn_g];
        const float* uS = &sU[nn_g * SSTR + bg * 32];
        const float* wS = &sW[nn_g * SSTR + dg * 32];

        float ur[4][8];
        #pragma unroll
        for (int i = 0; i < 4; ++i) {
            float4 a0 = *(const float4*)(uS + i * 8);
            float4 a1 = *(const float4*)(uS + i * 8 + 4);
            ur[i][0] = a0.x; ur[i][1] = a0.y; ur[i][2] = a0.z; ur[i][3] = a0.w;
            ur[i][4] = a1.x; ur[i][5] = a1.y; ur[i][6] = a1.z; ur[i][7] = a1.w;
        }
        #pragma unroll
        for (int j = 0; j < 4; ++j) {
            float4 w0 = *(const float4*)(wS + j * 8);
            float4 w1 = *(const float4*)(wS + j * 8 + 4);
            float w[8] = {w0.x, w0.y, w0.z, w0.w, w1.x, w1.y, w1.z, w1.w};
            #pragma unroll
            for (int i = 0; i < 4; ++i) {
                float dot = 0.f;
                #pragma unroll
                for (int p = 0; p < 8; ++p) dot = fmaf(w[p], ur[i][p], dot);
                acc[i][j] = sc * dot;
            }
        }
    }

    // ---- reduce over 16 nn lanes (half-warp shuffles)
    #pragma unroll
    for (int i = 0; i < 4; ++i)
        #pragma unroll
        for (int j = 0; j < 4; ++j) {
            float v = acc[i][j];
            #pragma unroll
            for (int off = 8; off >= 1; off >>= 1)
                v += __shfl_down_sync(0xFFFFFFFFu, v, off, 16);
            acc[i][j] = v;
        }

    if (nn_g == 0) {
        #pragma unroll
        for (int i = 0; i < 4; ++i)
            #pragma unroll
            for (int j = 0; j < 4; ++j)
                sOut[(bg * 4 + i) * DD + dg * 4 + j] = acc[i][j];
    }
    __syncthreads();

    // coalesced partial write: [m][chunk][t]
    const size_t pbase = ((size_t)m * NC + chunk) * (B_ * DD);
    g_partial[pbase + tid] = sOut[tid];

    // ---- last-CTA-per-m reduction + squash
    __threadfence();
    __syncthreads();
    if (tid == 0) sLast = atomicInc(&g_ctr[m], NC - 1);   // wraps to 0 -> self-reset
    __syncthreads();
    if (sLast != NC - 1) return;

    __threadfence();  // acquire side

    // thread t owns (b = t>>4, d = t&15); sum over 72 chunks (contiguous, coalesced)
    const float* pm = &g_partial[(size_t)m * NC * (B_ * DD)];
    float S = 0.f;
    #pragma unroll
    for (int c = 0; c < NC; ++c)
        S += __ldcg(pm + c * (B_ * DD) + tid);

    // norm over the 16 d-lanes (lane groups aligned within warps)
    float n2 = S * S;
    #pragma unroll
    for (int off = 8; off >= 1; off >>= 1)
        n2 += __shfl_xor_sync(0xFFFFFFFFu, n2, off, 16);

    const float norm  = sqrtf(n2);
    const float coef  = 1.0f - expf(-norm);
    const float scale = coef / (norm + 1e-7f);

    const int b = tid >> 4;
    const int d = tid & 15;
    out[((size_t)b * M_ + m) * DD + d] = S * scale;
}

extern "C" void kernel_launch(void* const* d_in, const int* in_sizes, int n_in,
                              void* d_out, int out_size)
{
    const float* u  = (const float*)d_in[0];   // primary_caps [16,1152,8]
    const float* W  = (const float*)d_in[1];   // W [10,1152,16,8]
    const float* Bp = (const float*)d_in[2];   // B_prior [10,1,1152]
    float* out = (float*)d_out;                // [16,10,16]

    dim3 grid(NC, M_);
    digitcaps_fused<<<grid, 256>>>(u, W, Bp, out);
}

// round 4
// speedup vs baseline: 1.8811x; 1.0517x over previous
#include <cuda_runtime.h>
#include <cuda_bf16.h>

typedef unsigned long long u64;

// Problem constants
#define B_   16      // batch
#define N_   1152    // primary caps
#define DP   8       // dim primary
#define M_   10      // digit caps
#define DD   16      // dim digit
#define CH   32      // n per chunk (one staging phase, 2 nn per thread)
#define NC   (N_ / CH)   // 36 chunks
#define SSTR 132     // padded stride per nn row (16*8 + 4), 16B-aligned, breaks bank cycles

// Partials [m][chunk][b*16+d]; counters zero-init, atomicInc wraps -> self-reset
__device__ float    g_partial[M_ * NC * B_ * DD];
__device__ unsigned g_ctr[M_];

__device__ __forceinline__ void fma2(u64& acc, u64 a, u64 b) {
    asm("fma.rn.f32x2 %0, %1, %2, %0;" : "+l"(acc) : "l"(a), "l"(b));
}

__global__ __launch_bounds__(256) void digitcaps_fused(
    const float* __restrict__ u,   // [B, N, DP]
    const float* __restrict__ W,   // [M, N, DD, DP]
    const float* __restrict__ Bp,  // [M, 1, N]
    float* __restrict__ out)       // [B, M, DD]
{
    __shared__ float sW[CH * SSTR];   // [nn][d*8 + zip(p)]  (pre-scaled by 1+Bp)
    __shared__ float sU[CH * SSTR];   // [nn][b*8 + zip(p)]
    __shared__ float sOut[B_ * DD];
    __shared__ unsigned sLast;

    const int chunk = blockIdx.x;     // 0..35
    const int m     = blockIdx.y;     // 0..9
    const int tid   = threadIdx.x;
    const int n0    = chunk * CH;

    // ---- stage W, zipped (p0,p4,p1,p5 | p2,p6,p3,p7), scaled by (1+Bp[m,n]).
    // 512 (nn,d) pairs, 2 per thread; lanes cover consecutive d -> coalesced.
    #pragma unroll
    for (int r = 0; r < 2; ++r) {
        const int f  = tid + r * 256;     // 0..511
        const int nn = f >> 4;            // 0..31
        const int d  = f & 15;
        const float sc = 1.0f + __ldg(&Bp[m * N_ + n0 + nn]);
        const float4* gw = (const float4*)(W + (((size_t)m * N_ + n0 + nn) * DD + d) * DP);
        const float4 a = gw[0];           // p0..p3
        const float4 c = gw[1];           // p4..p7
        float* s = &sW[nn * SSTR + d * 8];
        *(float4*)(s)     = make_float4(sc * a.x, sc * c.x, sc * a.y, sc * c.y);
        *(float4*)(s + 4) = make_float4(sc * a.z, sc * c.z, sc * a.w, sc * c.w);
    }
    // ---- stage u, zipped; (nn,b) pairs, lanes cover consecutive nn -> coalesced
    #pragma unroll
    for (int r = 0; r < 2; ++r) {
        const int f  = tid + r * 256;
        const int nn = (f & 15) + ((f >> 8) << 4);
        const int b  = (f >> 4) & 15;
        const float4* gu = (const float4*)(u + ((size_t)b * N_ + n0 + nn) * DP);
        const float4 a = gu[0];
        const float4 c = gu[1];
        float* s = &sU[nn * SSTR + b * 8];
        *(float4*)(s)     = make_float4(a.x, c.x, a.y, c.y);
        *(float4*)(s + 4) = make_float4(a.z, c.z, a.w, c.w);
    }
    __syncthreads();

    // ---- compute: thread (nn_g, bg, dg) does 4b x 4d for nn_g and nn_g+16
    const int nn_g = tid & 15;
    const int bg   = (tid >> 4) & 3;
    const int dg   = tid >> 6;

    u64 acc[4][4];
    #pragma unroll
    for (int i = 0; i < 4; ++i)
        #pragma unroll
        for (int j = 0; j < 4; ++j) acc[i][j] = 0ull;

    #pragma unroll
    for (int t = 0; t < 2; ++t) {
        const int nn = nn_g + 16 * t;
        const float* uS = &sU[nn * SSTR + bg * 32];
        const float* wS = &sW[nn * SSTR + dg * 32];

        ulonglong2 U0[4], U1[4];
        #pragma unroll
        for (int i = 0; i < 4; ++i) {
            U0[i] = *(const ulonglong2*)(uS + i * 8);      // pairs (k0,k1)
            U1[i] = *(const ulonglong2*)(uS + i * 8 + 4);  // pairs (k2,k3)
        }
        #pragma unroll
        for (int j = 0; j < 4; ++j) {
            const ulonglong2 w0 = *(const ulonglong2*)(wS + j * 8);
            const ulonglong2 w1 = *(const ulonglong2*)(wS + j * 8 + 4);
            #pragma unroll
            for (int i = 0; i < 4; ++i) {
                fma2(acc[i][j], U0[i].x, w0.x);
                fma2(acc[i][j], U0[i].y, w0.y);
                fma2(acc[i][j], U1[i].x, w1.x);
                fma2(acc[i][j], U1[i].y, w1.y);
            }
        }
    }

    // ---- collapse f32x2 halves, then reduce over the 16 nn lanes
    float S[4][4];
    #pragma unroll
    for (int i = 0; i < 4; ++i)
        #pragma unroll
        for (int j = 0; j < 4; ++j) {
            const u64 a = acc[i][j];
            const float lo = __uint_as_float((unsigned)(a & 0xffffffffu));
            const float hi = __uint_as_float((unsigned)(a >> 32));
            float v = lo + hi;
            #pragma unroll
            for (int off = 8; off >= 1; off >>= 1)
                v += __shfl_down_sync(0xFFFFFFFFu, v, off, 16);
            S[i][j] = v;
        }

    if (nn_g == 0) {
        #pragma unroll
        for (int i = 0; i < 4; ++i)
            #pragma unroll
            for (int j = 0; j < 4; ++j)
                sOut[(bg * 4 + i) * DD + dg * 4 + j] = S[i][j];
    }
    __syncthreads();

    // coalesced partial write: [m][chunk][tid]
    g_partial[((size_t)m * NC + chunk) * (B_ * DD) + tid] = sOut[tid];

    // ---- last CTA per m: reduce + squash
    __threadfence();
    __syncthreads();
    if (tid == 0) sLast = atomicInc(&g_ctr[m], NC - 1);  // wraps -> self-reset
    __syncthreads();
    if (sLast != NC - 1) return;

    __threadfence();

    const float* pm = &g_partial[(size_t)m * NC * (B_ * DD)];
    float Sv = 0.f;
    #pragma unroll
    for (int c = 0; c < NC; ++c)
        Sv += __ldcg(pm + c * (B_ * DD) + tid);

    float n2 = Sv * Sv;
    #pragma unroll
    for (int off = 8; off >= 1; off >>= 1)
        n2 += __shfl_xor_sync(0xFFFFFFFFu, n2, off, 16);

    const float norm  = sqrtf(n2);
    const float coef  = 1.0f - expf(-norm);
    const float scale = coef / (norm + 1e-7f);

    const int b = tid >> 4;
    const int d = tid & 15;
    out[((size_t)b * M_ + m) * DD + d] = Sv * scale;
}

extern "C" void kernel_launch(void* const* d_in, const int* in_sizes, int n_in,
                              void* d_out, int out_size)
{
    const float* u  = (const float*)d_in[0];   // primary_caps [16,1152,8]
    const float* W  = (const float*)d_in[1];   // W [10,1152,16,8]
    const float* Bp = (const float*)d_in[2];   // B_prior [10,1,1152]
    float* out = (float*)d_out;                // [16,10,16]

    dim3 grid(NC, M_);
    digitcaps_fused<<<grid, 256>>>(u, W, Bp, out);
}

// round 5
// speedup vs baseline: 1.8909x; 1.0052x over previous
#include <cuda_runtime.h>
#include <cuda_bf16.h>

typedef unsigned long long u64;

// Problem constants
#define B_   16      // batch
#define N_   1152    // primary caps
#define DP   8       // dim primary
#define M_   10      // digit caps
#define DD   16      // dim digit
#define CH   32      // n per chunk (one staging phase, 2 nn per thread)
#define NC   (N_ / CH)   // 36 chunks
#define SSTR 132     // padded stride per nn row (floats); 132 mod 32 = 4 -> conflict-free LDS.128 phases
#define RP   258     // padded row stride for u64 partial tile; even (16B align), 258*2 mod 32 = 4 -> conflict-free

#define STAGE_FLOATS (2 * CH * SSTR)          // sW + sU
#define SMEM_BYTES   (STAGE_FLOATS * 4)       // 33792 B; u64 tile 16*258*8 = 33024 B fits under it

// Partials [m][chunk][b*16+d]; counters zero-init, atomicInc wraps -> self-reset
__device__ float    g_partial[M_ * NC * B_ * DD];
__device__ unsigned g_ctr[M_];

__device__ __forceinline__ void fma2(u64& acc, u64 a, u64 b) {
    asm("fma.rn.f32x2 %0, %1, %2, %0;" : "+l"(acc) : "l"(a), "l"(b));
}
__device__ __forceinline__ void add2(u64& a, u64 b) {
    asm("add.rn.f32x2 %0, %0, %1;" : "+l"(a) : "l"(b));
}

__global__ __launch_bounds__(256) void digitcaps_fused(
    const float* __restrict__ u,   // [B, N, DP]
    const float* __restrict__ W,   // [M, N, DD, DP]
    const float* __restrict__ Bp,  // [M, 1, N]
    float* __restrict__ out)       // [B, M, DD]
{
    __shared__ __align__(16) char smem_raw[SMEM_BYTES];
    __shared__ unsigned sLast;

    float* sW = (float*)smem_raw;              // [nn][d*8 + zip(p)] pre-scaled by (1+Bp)
    float* sU = sW + CH * SSTR;                // [nn][b*8 + zip(p)]
    u64*   sP = (u64*)smem_raw;                // overlay: [16 nn][258] u64 partials

    const int chunk = blockIdx.x;     // 0..35
    const int m     = blockIdx.y;     // 0..9
    const int tid   = threadIdx.x;
    const int n0    = chunk * CH;

    // ---- stage W, zipped (p0,p4,p1,p5 | p2,p6,p3,p7), scaled by (1+Bp[m,n])
    #pragma unroll
    for (int r = 0; r < 2; ++r) {
        const int f  = tid + r * 256;     // 0..511 (nn,d) pairs
        const int nn = f >> 4;
        const int d  = f & 15;
        const float sc = 1.0f + __ldg(&Bp[m * N_ + n0 + nn]);
        const float4* gw = (const float4*)(W + (((size_t)m * N_ + n0 + nn) * DD + d) * DP);
        const float4 a = gw[0];           // p0..p3
        const float4 c = gw[1];           // p4..p7
        float* s = &sW[nn * SSTR + d * 8];
        *(float4*)(s)     = make_float4(sc * a.x, sc * c.x, sc * a.y, sc * c.y);
        *(float4*)(s + 4) = make_float4(sc * a.z, sc * c.z, sc * a.w, sc * c.w);
    }
    // ---- stage u, zipped; (nn,b) pairs
    #pragma unroll
    for (int r = 0; r < 2; ++r) {
        const int f  = tid + r * 256;
        const int nn = (f & 15) + ((f >> 8) << 4);
        const int b  = (f >> 4) & 15;
        const float4* gu = (const float4*)(u + ((size_t)b * N_ + n0 + nn) * DP);
        const float4 a = gu[0];
        const float4 c = gu[1];
        float* s = &sU[nn * SSTR + b * 8];
        *(float4*)(s)     = make_float4(a.x, c.x, a.y, c.y);
        *(float4*)(s + 4) = make_float4(a.z, c.z, a.w, c.w);
    }
    __syncthreads();

    // ---- compute: thread (nn_g, bg, dg) does 4b x 4d for nn_g and nn_g+16
    const int nn_g = tid & 15;
    const int bg   = (tid >> 4) & 3;
    const int dg   = tid >> 6;

    u64 acc[4][4];
    #pragma unroll
    for (int i = 0; i < 4; ++i)
        #pragma unroll
        for (int j = 0; j < 4; ++j) acc[i][j] = 0ull;

    #pragma unroll
    for (int t = 0; t < 2; ++t) {
        const int nn = nn_g + 16 * t;
        const float* uS = &sU[nn * SSTR + bg * 32];
        const float* wS = &sW[nn * SSTR + dg * 32];

        ulonglong2 U0[4], U1[4];
        #pragma unroll
        for (int i = 0; i < 4; ++i) {
            U0[i] = *(const ulonglong2*)(uS + i * 8);      // pairs (k0,k1)
            U1[i] = *(const ulonglong2*)(uS + i * 8 + 4);  // pairs (k2,k3)
        }
        #pragma unroll
        for (int j = 0; j < 4; ++j) {
            const ulonglong2 w0 = *(const ulonglong2*)(wS + j * 8);
            const ulonglong2 w1 = *(const ulonglong2*)(wS + j * 8 + 4);
            #pragma unroll
            for (int i = 0; i < 4; ++i) {
                fma2(acc[i][j], U0[i].x, w0.x);
                fma2(acc[i][j], U0[i].y, w0.y);
                fma2(acc[i][j], U1[i].x, w1.x);
                fma2(acc[i][j], U1[i].y, w1.y);
            }
        }
    }

    // ---- smem transpose reduce over the 16 nn lanes (replaces shuffles)
    __syncthreads();   // all sW/sU reads done before overlay write

    {
        u64* row = sP + (size_t)nn_g * RP;
        #pragma unroll
        for (int i = 0; i < 4; ++i) {
            const int bd = (bg * 4 + i) * DD + dg * 4;
            *(ulonglong2*)(row + bd)     = make_ulonglong2(acc[i][0], acc[i][1]);
            *(ulonglong2*)(row + bd + 2) = make_ulonglong2(acc[i][2], acc[i][3]);
        }
    }
    __syncthreads();

    // thread tid owns output element bd = tid: sum 16 nn rows, packed adds
    u64 v = sP[tid];
    #pragma unroll
    for (int nn = 1; nn < 16; ++nn) add2(v, sP[(size_t)nn * RP + tid]);
    const float S = __uint_as_float((unsigned)(v & 0xffffffffu)) +
                    __uint_as_float((unsigned)(v >> 32));

    // coalesced partial write: [m][chunk][tid]
    g_partial[((size_t)m * NC + chunk) * (B_ * DD) + tid] = S;

    // ---- last CTA per m: reduce + squash
    __threadfence();
    __syncthreads();
    if (tid == 0) sLast = atomicInc(&g_ctr[m], NC - 1);  // wraps -> self-reset
    __syncthreads();
    if (sLast != NC - 1) return;

    __threadfence();

    const float* pm = &g_partial[(size_t)m * NC * (B_ * DD)];
    float Sv = 0.f;
    #pragma unroll
    for (int c = 0; c < NC; ++c)
        Sv += __ldcg(pm + c * (B_ * DD) + tid);

    float n2 = Sv * Sv;
    #pragma unroll
    for (int off = 8; off >= 1; off >>= 1)
        n2 += __shfl_xor_sync(0xFFFFFFFFu, n2, off, 16);

    const float norm  = sqrtf(n2);
    const float coef  = 1.0f - expf(-norm);
    const float scale = coef / (norm + 1e-7f);

    const int b = tid >> 4;
    const int d = tid & 15;
    out[((size_t)b * M_ + m) * DD + d] = Sv * scale;
}

extern "C" void kernel_launch(void* const* d_in, const int* in_sizes, int n_in,
                              void* d_out, int out_size)
{
    const float* u  = (const float*)d_in[0];   // primary_caps [16,1152,8]
    const float* W  = (const float*)d_in[1];   // W [10,1152,16,8]
    const float* Bp = (const float*)d_in[2];   // B_prior [10,1,1152]
    float* out = (float*)d_out;                // [16,10,16]

    dim3 grid(NC, M_);
    digitcaps_fused<<<grid, 256>>>(u, W, Bp, out);
}